// round 12
// baseline (speedup 1.0000x reference)
#include <cuda_runtime.h>
#include <math.h>

#define NG 4096
#define W_IMG 256
#define H_IMG 256
#define TSZ 64
#define NBLK 256           // 16x16 grid of 16x16-pixel blocks
#define NTHR 256
#define GPT 16             // gaussians per thread in strip scan

// unsorted per-gaussian data (attr-packed)
__device__ float  g_zraw[NG];
__device__ int    g_rank[NG];
__device__ float4 g_tA[NG];     // mx,my,c00,c11
__device__ float2 g_tQ[NG];     // csum,op
__device__ float4 g_tR[NG];     // r,g,b,z
__device__ unsigned g_tpbx[NG]; // packed bbox bytes {xmin,xmax,ymin,ymax}, tile-expanded if clipped

// z-sorted
__device__ float4 g_sA[NG];
__device__ float2 g_sQ[NG];
__device__ float4 g_sR[NG];
__device__ unsigned g_spbx[NG];

// ---------------------------------------------------------------------------
// Kernel 1: projection / preprocessing
// ---------------------------------------------------------------------------
__global__ void prep_kernel(const float* __restrict__ xyz,
                            const float* __restrict__ cov_world,
                            const float* __restrict__ colors,
                            const float* __restrict__ opacity,
                            const float* __restrict__ w2c,
                            const float* __restrict__ focal,
                            const float* __restrict__ pp)
{
    int i = blockIdx.x * blockDim.x + threadIdx.x;
    if (i >= NG) return;

    float R00 = w2c[0],  R01 = w2c[1],  R02 = w2c[2],  t0 = w2c[3];
    float R10 = w2c[4],  R11 = w2c[5],  R12 = w2c[6],  t1 = w2c[7];
    float R20 = w2c[8],  R21 = w2c[9],  R22 = w2c[10], t2 = w2c[11];

    float p0 = xyz[i*3+0], p1 = xyz[i*3+1], p2 = xyz[i*3+2];
    float cam0 = R00*p0 + R01*p1 + R02*p2 + t0;
    float cam1 = R10*p0 + R11*p1 + R12*p2 + t1;
    float cam2 = R20*p0 + R21*p1 + R22*p2 + t2;

    float zr = cam2;
    float z  = fmaxf(zr, 1e-6f);
    float fx = focal[0], fy = focal[1];
    float mx = fx * cam0 / z + pp[0];
    float my = fy * cam1 / z + pp[1];

    float S[3][3];
    #pragma unroll
    for (int r = 0; r < 3; r++)
        #pragma unroll
        for (int c = 0; c < 3; c++)
            S[r][c] = cov_world[i*9 + r*3 + c];

    float Rm[3][3] = {{R00,R01,R02},{R10,R11,R12},{R20,R21,R22}};
    float M[3][3], C[3][3];
    #pragma unroll
    for (int r = 0; r < 3; r++)
        #pragma unroll
        for (int c = 0; c < 3; c++)
            M[r][c] = Rm[r][0]*S[0][c] + Rm[r][1]*S[1][c] + Rm[r][2]*S[2][c];
    #pragma unroll
    for (int r = 0; r < 3; r++)
        #pragma unroll
        for (int c = 0; c < 3; c++)
            C[r][c] = M[r][0]*Rm[c][0] + M[r][1]*Rm[c][1] + M[r][2]*Rm[c][2];

    float J00 = fx / z, J02 = -fx * cam0 / (z * z);
    float J11 = fy / z, J12 = -fy * cam1 / (z * z);
    float t0v0 = J00*C[0][0] + J02*C[2][0];
    float t0v1 = J00*C[0][1] + J02*C[2][1];
    float t0v2 = J00*C[0][2] + J02*C[2][2];
    float t1v0 = J11*C[1][0] + J12*C[2][0];
    float t1v1 = J11*C[1][1] + J12*C[2][1];
    float t1v2 = J11*C[1][2] + J12*C[2][2];

    float a = t0v0*J00 + t0v2*J02 + 0.3f;
    float b = t0v1*J11 + t0v2*J12;
    float c = t1v0*J00 + t1v2*J02;
    float d = t1v1*J11 + t1v2*J12 + 0.3f;

    float disc   = sqrtf(fmaxf(0.25f*(a-d)*(a-d) + b*c, 0.0f));
    float maxeig = fmaxf(0.5f*(a+d) + disc, 1e-8f);
    float rraw   = 3.0f * sqrtf(maxeig);
    float radius = fminf(rraw, 64.0f);
    float det    = a*d - b*c;
    float c00  = d / det;
    float c11  = a / det;
    float csum = (-b - c) / det;

    float opv = opacity[i];
    bool valid = (zr > 0.1f) && (opv > 1e-4f) && (radius > 0.25f);
    valid = valid && (mx + radius >= -1.0f) && (mx - radius < (float)W_IMG + 1.0f);
    valid = valid && (my + radius >= -1.0f) && (my - radius < (float)H_IMG + 1.0f);

    float radii = ceilf(radius);
    int ixmin = (int)fminf(fmaxf(floorf(mx - radii), 0.0f), 255.0f);
    int ixmax = (int)fminf(fmaxf(ceilf (mx + radii), 0.0f), 255.0f);
    int iymin = (int)fminf(fmaxf(floorf(my - radii), 0.0f), 255.0f);
    int iymax = (int)fminf(fmaxf(ceilf (my + radii), 0.0f), 255.0f);

    // Clipped radius: 3-sigma ellipse may exceed bbox, so the per-block bbox
    // refine is unsound; expand bbox to tile boundaries, making the block
    // interval test exactly equivalent to the reference tile-overlap test.
    if (rraw > 64.0f) {
        ixmin &= ~63; iymin &= ~63;
        ixmax |=  63; iymax |=  63;
    }

    unsigned pbx;
    if (!valid) {
        pbx = 255u | (0u << 8) | (255u << 16) | (0u << 24);   // empty bbox
    } else {
        pbx = (unsigned)ixmin | ((unsigned)ixmax << 8) |
              ((unsigned)iymin << 16) | ((unsigned)iymax << 24);
    }

    g_zraw[i] = zr;
    g_rank[i] = 0;
    g_tA[i] = make_float4(mx, my, c00, c11);
    g_tQ[i] = make_float2(csum, opv);
    g_tR[i] = make_float4(colors[i*3+0], colors[i*3+1], colors[i*3+2], zr);
    g_tpbx[i] = pbx;
}

// ---------------------------------------------------------------------------
// Kernel 2: partial stable rank. grid = (16 i-chunks, 16 j-chunks).
// ---------------------------------------------------------------------------
__global__ void __launch_bounds__(256)
rank_kernel()
{
    __shared__ float zsh[256];
    const int ibase = blockIdx.x * 256;
    const int jbase = blockIdx.y * 256;
    const int tid = threadIdx.x;

    zsh[tid] = g_zraw[jbase + tid];
    __syncthreads();

    const int i = ibase + tid;
    const float zi = g_zraw[i];
    const float4* z4 = (const float4*)zsh;
    int partial = 0;
    #pragma unroll 8
    for (int j4 = 0; j4 < 64; j4++) {
        float4 v = z4[j4];
        int j = jbase + j4 * 4;
        partial += (v.x < zi) || (v.x == zi && (j+0) < i);
        partial += (v.y < zi) || (v.y == zi && (j+1) < i);
        partial += (v.z < zi) || (v.z == zi && (j+2) < i);
        partial += (v.w < zi) || (v.w == zi && (j+3) < i);
    }
    atomicAdd(&g_rank[i], partial);
}

// ---------------------------------------------------------------------------
// Kernel 3: scatter to sorted order
// ---------------------------------------------------------------------------
__global__ void scatter_kernel()
{
    int i = blockIdx.x * blockDim.x + threadIdx.x;
    if (i >= NG) return;
    int r = g_rank[i];
    g_sA[r]   = g_tA[i];
    g_sQ[r]   = g_tQ[i];
    g_sR[r]   = g_tR[i];
    g_spbx[r] = g_tpbx[i];
}

// ---------------------------------------------------------------------------
// Kernel 4: fused bin + rasterize. One block = one 16x16 pixel block.
// Block index remapped center-first so heavy blocks start in wave 1.
// Phase A: strip-scan predicates (SIMD byte compares), block scan, ordered
//          index list in shared. Phase B: unroll-2 composite loop.
// ---------------------------------------------------------------------------
__device__ __forceinline__ int center_first(int k)
{
    // 0,1,2,3,... -> 7,8,6,9,5,10,4,11,3,12,2,13,1,14,0,15
    int off = (k + 1) >> 1;
    return 7 + ((k & 1) ? off : -off);
}

__global__ void __launch_bounds__(NTHR)
render_kernel(const float* __restrict__ bg, float* __restrict__ out)
{
    const int bl  = blockIdx.x;
    const int bx0 = center_first(bl & 15) * 16;
    const int by0 = center_first(bl >> 4) * 16;

    const int tid  = threadIdx.x;
    const int warp = tid >> 5;
    const int lane = tid & 31;

    __shared__ short s_idx[NG];
    __shared__ int wsum[8], wpre[8];
    __shared__ float4 sP[NTHR];
    __shared__ float2 sQ[NTHR];
    __shared__ float4 sR[NTHR];

    // SIMD thresholds: bytes of pbx are {xmin, xmax, ymin, ymax}
    const unsigned Tge = ((unsigned)bx0 << 8) | ((unsigned)by0 << 24);
    const unsigned Tle = (unsigned)(bx0 + 15) | (255u << 8) |
                         ((unsigned)(by0 + 15) << 16) | (255u << 24);

    // --- Phase A: predicates, 4 x LDG.128 per thread = 16 gaussians ---
    const uint4* pb4 = (const uint4*)g_spbx;
    unsigned mmask = 0;
    int lc = 0;
    #pragma unroll
    for (int q = 0; q < 4; q++) {
        uint4 p = pb4[tid * 4 + q];
        unsigned w0 = __vcmpgeu4(p.x, Tge) & __vcmpleu4(p.x, Tle);
        unsigned w1 = __vcmpgeu4(p.y, Tge) & __vcmpleu4(p.y, Tle);
        unsigned w2 = __vcmpgeu4(p.z, Tge) & __vcmpleu4(p.z, Tle);
        unsigned w3 = __vcmpgeu4(p.w, Tge) & __vcmpleu4(p.w, Tle);
        if (w0 == 0xFFFFFFFFu) { mmask |= 1u << (q*4+0); lc++; }
        if (w1 == 0xFFFFFFFFu) { mmask |= 1u << (q*4+1); lc++; }
        if (w2 == 0xFFFFFFFFu) { mmask |= 1u << (q*4+2); lc++; }
        if (w3 == 0xFFFFFFFFu) { mmask |= 1u << (q*4+3); lc++; }
    }

    // --- block-wide exclusive scan of lc ---
    int v = lc;
    #pragma unroll
    for (int d2 = 1; d2 < 32; d2 <<= 1) {
        int n = __shfl_up_sync(0xffffffffu, v, d2);
        if (lane >= d2) v += n;
    }
    if (lane == 31) wsum[warp] = v;
    __syncthreads();
    if (tid < 8) {
        int s = wsum[tid];
        #pragma unroll
        for (int d2 = 1; d2 < 8; d2 <<= 1) {
            int n = __shfl_up_sync(0xffu, s, d2);
            if (tid >= d2) s += n;
        }
        wpre[tid] = s;
    }
    __syncthreads();

    int offset = ((warp == 0) ? 0 : wpre[warp - 1]) + (v - lc);
    const int base = tid * GPT;
    unsigned mm = mmask;
    while (mm) {
        int k = __ffs(mm) - 1;
        mm &= mm - 1;
        s_idx[offset++] = (short)(base + k);
    }
    const int cnt = wpre[7];
    __syncthreads();

    // --- Phase B: composite (unroll-2) ---
    const int px = bx0 + (tid & 15);
    const int py = by0 + (tid >> 4);
    const float cx = (float)px + 0.5f;
    const float cy = (float)py + 0.5f;

    float T = 1.0f;
    float accR = 0.f, accG = 0.f, accB = 0.f, acc = 0.f, dnum = 0.f;

    for (int cbase = 0; cbase < cnt; cbase += NTHR) {
        int li = cbase + tid;
        if (li < cnt) {
            int gi = s_idx[li];
            sP[tid] = g_sA[gi];
            sQ[tid] = g_sQ[gi];
            sR[tid] = g_sR[gi];
        }
        __syncthreads();

        int m = cnt - cbase; if (m > NTHR) m = NTHR;
        int k = 0;
        for (; k + 2 <= m; k += 2) {
            float4 P0 = sP[k],   P1 = sP[k+1];
            float2 Q0 = sQ[k],   Q1 = sQ[k+1];
            float dx0 = cx - P0.x, dy0 = cy - P0.y;
            float dx1 = cx - P1.x, dy1 = cy - P1.y;
            float maha0 = dx0*dx0*P0.z + dy0*dy0*P0.w + dx0*dy0*Q0.x;
            float maha1 = dx1*dx1*P1.z + dy1*dy1*P1.w + dx1*dy1*Q1.x;
            bool hit0 = (maha0 <= 9.0f);      // NaN -> false, matches jnp.where
            bool hit1 = (maha1 <= 9.0f);
            if (__any_sync(0xffffffffu, hit0 || hit1)) {
                float alpha0 = fminf(__expf(-0.5f * maha0) * Q0.y, 0.99f);
                if (hit0 && alpha0 >= (1.0f / 255.0f)) {
                    float4 Cv = sR[k];
                    float w = T * alpha0;
                    accR += w * Cv.x;
                    accG += w * Cv.y;
                    accB += w * Cv.z;
                    acc  += w;
                    dnum += w * Cv.w;
                    T *= (1.0f - alpha0);
                }
                float alpha1 = fminf(__expf(-0.5f * maha1) * Q1.y, 0.99f);
                if (hit1 && alpha1 >= (1.0f / 255.0f)) {
                    float4 Cv = sR[k+1];
                    float w = T * alpha1;
                    accR += w * Cv.x;
                    accG += w * Cv.y;
                    accB += w * Cv.z;
                    acc  += w;
                    dnum += w * Cv.w;
                    T *= (1.0f - alpha1);
                }
            }
        }
        if (k < m) {
            float4 P0 = sP[k];
            float2 Q0 = sQ[k];
            float dx0 = cx - P0.x, dy0 = cy - P0.y;
            float maha0 = dx0*dx0*P0.z + dy0*dy0*P0.w + dx0*dy0*Q0.x;
            bool hit0 = (maha0 <= 9.0f);
            if (__any_sync(0xffffffffu, hit0)) {
                float alpha0 = fminf(__expf(-0.5f * maha0) * Q0.y, 0.99f);
                if (hit0 && alpha0 >= (1.0f / 255.0f)) {
                    float4 Cv = sR[k];
                    float w = T * alpha0;
                    accR += w * Cv.x;
                    accG += w * Cv.y;
                    accB += w * Cv.z;
                    acc  += w;
                    dnum += w * Cv.w;
                    T *= (1.0f - alpha0);
                }
            }
        }

        if (cbase + NTHR < cnt) {
            if (__syncthreads_and(T < 1e-7f)) break;
        }
    }

    float bgr = bg[0], bgg = bg[1], bgb = bg[2];
    float Rv = accR + (1.0f - acc) * bgr;
    float Gv = accG + (1.0f - acc) * bgg;
    float Bv = accB + (1.0f - acc) * bgb;
    Rv = fminf(fmaxf(Rv, 0.0f), 1.0f);
    Gv = fminf(fmaxf(Gv, 0.0f), 1.0f);
    Bv = fminf(fmaxf(Bv, 0.0f), 1.0f);
    float A = fminf(fmaxf(acc, 0.0f), 1.0f);
    float depth = (acc > 0.0f) ? (dnum / fmaxf(acc, 1e-8f)) : 0.0f;

    int o = (py * W_IMG + px) * 5;
    out[o+0] = Rv;
    out[o+1] = Gv;
    out[o+2] = Bv;
    out[o+3] = A;
    out[o+4] = depth;
}

// ---------------------------------------------------------------------------
extern "C" void kernel_launch(void* const* d_in, const int* in_sizes, int n_in,
                              void* d_out, int out_size)
{
    const float* xyz     = (const float*)d_in[0];
    const float* cov     = (const float*)d_in[1];
    const float* colors  = (const float*)d_in[2];
    const float* opacity = (const float*)d_in[3];
    const float* w2c     = (const float*)d_in[4];
    const float* focal   = (const float*)d_in[5];
    const float* pp      = (const float*)d_in[6];
    const float* bg      = (const float*)d_in[7];
    float* out = (float*)d_out;

    prep_kernel<<<NG / 64, 64>>>(xyz, cov, colors, opacity, w2c, focal, pp);
    rank_kernel<<<dim3(16, 16), 256>>>();
    scatter_kernel<<<NG / 256, 256>>>();
    render_kernel<<<NBLK, NTHR>>>(bg, out);
}

// round 13
// speedup vs baseline: 1.0033x; 1.0033x over previous
#include <cuda_runtime.h>
#include <math.h>

#define NG 4096
#define W_IMG 256
#define H_IMG 256
#define TSZ 64
#define NBLK 256           // 16x16 grid of 16x16-pixel blocks
#define NTHR 256
#define NSEG 2             // z-list split factor
#define SEGN (NG / NSEG)   // gaussians per segment
#define GPT  (SEGN / NTHR) // gaussians per thread in strip scan (8)
#define NPIX (W_IMG * H_IMG)

// unsorted per-gaussian data (attr-packed)
__device__ float  g_zraw[NG];
__device__ int    g_rank[NG];
__device__ float4 g_tA[NG];     // mx,my,c00,c11
__device__ float2 g_tQ[NG];     // csum,op
__device__ float4 g_tR[NG];     // r,g,b,z
__device__ unsigned g_tpbx[NG]; // packed bbox bytes {xmin,xmax,ymin,ymax}, tile-expanded if clipped

// z-sorted
__device__ float4 g_sA[NG];
__device__ float2 g_sQ[NG];
__device__ float4 g_sR[NG];
__device__ unsigned g_spbx[NG];

// per-(segment, pixel) compositing partials
__device__ float4 g_p4[NSEG][NPIX];   // accR, accG, accB, acc
__device__ float2 g_p2[NSEG][NPIX];   // dnum, T

// ---------------------------------------------------------------------------
// Kernel 1: projection / preprocessing
// ---------------------------------------------------------------------------
__global__ void prep_kernel(const float* __restrict__ xyz,
                            const float* __restrict__ cov_world,
                            const float* __restrict__ colors,
                            const float* __restrict__ opacity,
                            const float* __restrict__ w2c,
                            const float* __restrict__ focal,
                            const float* __restrict__ pp)
{
    int i = blockIdx.x * blockDim.x + threadIdx.x;
    if (i >= NG) return;

    float R00 = w2c[0],  R01 = w2c[1],  R02 = w2c[2],  t0 = w2c[3];
    float R10 = w2c[4],  R11 = w2c[5],  R12 = w2c[6],  t1 = w2c[7];
    float R20 = w2c[8],  R21 = w2c[9],  R22 = w2c[10], t2 = w2c[11];

    float p0 = xyz[i*3+0], p1 = xyz[i*3+1], p2 = xyz[i*3+2];
    float cam0 = R00*p0 + R01*p1 + R02*p2 + t0;
    float cam1 = R10*p0 + R11*p1 + R12*p2 + t1;
    float cam2 = R20*p0 + R21*p1 + R22*p2 + t2;

    float zr = cam2;
    float z  = fmaxf(zr, 1e-6f);
    float fx = focal[0], fy = focal[1];
    float mx = fx * cam0 / z + pp[0];
    float my = fy * cam1 / z + pp[1];

    float S[3][3];
    #pragma unroll
    for (int r = 0; r < 3; r++)
        #pragma unroll
        for (int c = 0; c < 3; c++)
            S[r][c] = cov_world[i*9 + r*3 + c];

    float Rm[3][3] = {{R00,R01,R02},{R10,R11,R12},{R20,R21,R22}};
    float M[3][3], C[3][3];
    #pragma unroll
    for (int r = 0; r < 3; r++)
        #pragma unroll
        for (int c = 0; c < 3; c++)
            M[r][c] = Rm[r][0]*S[0][c] + Rm[r][1]*S[1][c] + Rm[r][2]*S[2][c];
    #pragma unroll
    for (int r = 0; r < 3; r++)
        #pragma unroll
        for (int c = 0; c < 3; c++)
            C[r][c] = M[r][0]*Rm[c][0] + M[r][1]*Rm[c][1] + M[r][2]*Rm[c][2];

    float J00 = fx / z, J02 = -fx * cam0 / (z * z);
    float J11 = fy / z, J12 = -fy * cam1 / (z * z);
    float t0v0 = J00*C[0][0] + J02*C[2][0];
    float t0v1 = J00*C[0][1] + J02*C[2][1];
    float t0v2 = J00*C[0][2] + J02*C[2][2];
    float t1v0 = J11*C[1][0] + J12*C[2][0];
    float t1v1 = J11*C[1][1] + J12*C[2][1];
    float t1v2 = J11*C[1][2] + J12*C[2][2];

    float a = t0v0*J00 + t0v2*J02 + 0.3f;
    float b = t0v1*J11 + t0v2*J12;
    float c = t1v0*J00 + t1v2*J02;
    float d = t1v1*J11 + t1v2*J12 + 0.3f;

    float disc   = sqrtf(fmaxf(0.25f*(a-d)*(a-d) + b*c, 0.0f));
    float maxeig = fmaxf(0.5f*(a+d) + disc, 1e-8f);
    float rraw   = 3.0f * sqrtf(maxeig);
    float radius = fminf(rraw, 64.0f);
    float det    = a*d - b*c;
    float c00  = d / det;
    float c11  = a / det;
    float csum = (-b - c) / det;

    float opv = opacity[i];
    bool valid = (zr > 0.1f) && (opv > 1e-4f) && (radius > 0.25f);
    valid = valid && (mx + radius >= -1.0f) && (mx - radius < (float)W_IMG + 1.0f);
    valid = valid && (my + radius >= -1.0f) && (my - radius < (float)H_IMG + 1.0f);

    float radii = ceilf(radius);
    int ixmin = (int)fminf(fmaxf(floorf(mx - radii), 0.0f), 255.0f);
    int ixmax = (int)fminf(fmaxf(ceilf (mx + radii), 0.0f), 255.0f);
    int iymin = (int)fminf(fmaxf(floorf(my - radii), 0.0f), 255.0f);
    int iymax = (int)fminf(fmaxf(ceilf (my + radii), 0.0f), 255.0f);

    // Clipped radius: 3-sigma ellipse may exceed bbox, so the per-block bbox
    // refine is unsound; expand bbox to tile boundaries, making the block
    // interval test exactly equivalent to the reference tile-overlap test.
    if (rraw > 64.0f) {
        ixmin &= ~63; iymin &= ~63;
        ixmax |=  63; iymax |=  63;
    }

    unsigned pbx;
    if (!valid) {
        pbx = 255u | (0u << 8) | (255u << 16) | (0u << 24);   // empty bbox
    } else {
        pbx = (unsigned)ixmin | ((unsigned)ixmax << 8) |
              ((unsigned)iymin << 16) | ((unsigned)iymax << 24);
    }

    g_zraw[i] = zr;
    g_rank[i] = 0;
    g_tA[i] = make_float4(mx, my, c00, c11);
    g_tQ[i] = make_float2(csum, opv);
    g_tR[i] = make_float4(colors[i*3+0], colors[i*3+1], colors[i*3+2], zr);
    g_tpbx[i] = pbx;
}

// ---------------------------------------------------------------------------
// Kernel 2: partial stable rank. grid = (16 i-chunks, 16 j-chunks).
// ---------------------------------------------------------------------------
__global__ void __launch_bounds__(256)
rank_kernel()
{
    __shared__ float zsh[256];
    const int ibase = blockIdx.x * 256;
    const int jbase = blockIdx.y * 256;
    const int tid = threadIdx.x;

    zsh[tid] = g_zraw[jbase + tid];
    __syncthreads();

    const int i = ibase + tid;
    const float zi = g_zraw[i];
    const float4* z4 = (const float4*)zsh;
    int partial = 0;
    #pragma unroll 8
    for (int j4 = 0; j4 < 64; j4++) {
        float4 v = z4[j4];
        int j = jbase + j4 * 4;
        partial += (v.x < zi) || (v.x == zi && (j+0) < i);
        partial += (v.y < zi) || (v.y == zi && (j+1) < i);
        partial += (v.z < zi) || (v.z == zi && (j+2) < i);
        partial += (v.w < zi) || (v.w == zi && (j+3) < i);
    }
    atomicAdd(&g_rank[i], partial);
}

// ---------------------------------------------------------------------------
// Kernel 3: scatter to sorted order
// ---------------------------------------------------------------------------
__global__ void scatter_kernel()
{
    int i = blockIdx.x * blockDim.x + threadIdx.x;
    if (i >= NG) return;
    int r = g_rank[i];
    g_sA[r]   = g_tA[i];
    g_sQ[r]   = g_tQ[i];
    g_sR[r]   = g_tR[i];
    g_spbx[r] = g_tpbx[i];
}

// ---------------------------------------------------------------------------
// Kernel 4: fused bin + rasterize, split-K over the sorted z-list.
// CTA = (pixel-block bl, z-segment seg). Segment scans only its 2048
// gaussians (total Phase A work unchanged vs unsplit) and composites
// partials {accRGB, acc, dnum, T} for its half-list.
// ---------------------------------------------------------------------------
__global__ void __launch_bounds__(NTHR)
render_kernel()
{
    const int bl  = blockIdx.x & (NBLK - 1);
    const int seg = blockIdx.x >> 8;
    const int bx0 = (bl & 15) * 16;
    const int by0 = (bl >> 4) * 16;
    const int gbase = seg * SEGN;

    const int tid  = threadIdx.x;
    const int warp = tid >> 5;
    const int lane = tid & 31;

    __shared__ short s_idx[SEGN];
    __shared__ int wsum[8], wpre[8];
    __shared__ float4 sP[NTHR];
    __shared__ float2 sQ[NTHR];
    __shared__ float4 sR[NTHR];

    // SIMD thresholds: bytes of pbx are {xmin, xmax, ymin, ymax}
    const unsigned Tge = ((unsigned)bx0 << 8) | ((unsigned)by0 << 24);
    const unsigned Tle = (unsigned)(bx0 + 15) | (255u << 8) |
                         ((unsigned)(by0 + 15) << 16) | (255u << 24);

    // --- Phase A: predicates, 2 x LDG.128 per thread = 8 gaussians ---
    const uint4* pb4 = (const uint4*)(g_spbx + gbase);
    unsigned mmask = 0;
    int lc = 0;
    #pragma unroll
    for (int q = 0; q < GPT / 4; q++) {
        uint4 p = pb4[tid * (GPT / 4) + q];
        unsigned w0 = __vcmpgeu4(p.x, Tge) & __vcmpleu4(p.x, Tle);
        unsigned w1 = __vcmpgeu4(p.y, Tge) & __vcmpleu4(p.y, Tle);
        unsigned w2 = __vcmpgeu4(p.z, Tge) & __vcmpleu4(p.z, Tle);
        unsigned w3 = __vcmpgeu4(p.w, Tge) & __vcmpleu4(p.w, Tle);
        if (w0 == 0xFFFFFFFFu) { mmask |= 1u << (q*4+0); lc++; }
        if (w1 == 0xFFFFFFFFu) { mmask |= 1u << (q*4+1); lc++; }
        if (w2 == 0xFFFFFFFFu) { mmask |= 1u << (q*4+2); lc++; }
        if (w3 == 0xFFFFFFFFu) { mmask |= 1u << (q*4+3); lc++; }
    }

    // --- block-wide exclusive scan of lc ---
    int v = lc;
    #pragma unroll
    for (int d2 = 1; d2 < 32; d2 <<= 1) {
        int n = __shfl_up_sync(0xffffffffu, v, d2);
        if (lane >= d2) v += n;
    }
    if (lane == 31) wsum[warp] = v;
    __syncthreads();
    if (tid < 8) {
        int s = wsum[tid];
        #pragma unroll
        for (int d2 = 1; d2 < 8; d2 <<= 1) {
            int n = __shfl_up_sync(0xffu, s, d2);
            if (tid >= d2) s += n;
        }
        wpre[tid] = s;
    }
    __syncthreads();

    int offset = ((warp == 0) ? 0 : wpre[warp - 1]) + (v - lc);
    const int base = tid * GPT;          // segment-local
    unsigned mm = mmask;
    while (mm) {
        int k = __ffs(mm) - 1;
        mm &= mm - 1;
        s_idx[offset++] = (short)(base + k);
    }
    const int cnt = wpre[7];
    __syncthreads();

    // --- Phase B: composite this segment ---
    const int px = bx0 + (tid & 15);
    const int py = by0 + (tid >> 4);
    const float cx = (float)px + 0.5f;
    const float cy = (float)py + 0.5f;

    float T = 1.0f;
    float accR = 0.f, accG = 0.f, accB = 0.f, acc = 0.f, dnum = 0.f;

    for (int cbase = 0; cbase < cnt; cbase += NTHR) {
        int li = cbase + tid;
        if (li < cnt) {
            int gi = gbase + s_idx[li];
            sP[tid] = g_sA[gi];
            sQ[tid] = g_sQ[gi];
            sR[tid] = g_sR[gi];
        }
        __syncthreads();

        int m = cnt - cbase; if (m > NTHR) m = NTHR;
        for (int k = 0; k < m; k++) {
            float4 P = sP[k];
            float dx = cx - P.x;
            float dy = cy - P.y;
            float2 Q = sQ[k];
            float maha = dx*dx*P.z + dy*dy*P.w + dx*dy*Q.x;
            bool hit = (maha <= 9.0f);        // NaN -> false, matches jnp.where
            if (__any_sync(0xffffffffu, hit)) {
                float alpha = fminf(__expf(-0.5f * maha) * Q.y, 0.99f);
                if (hit && alpha >= (1.0f / 255.0f)) {
                    float4 Cv = sR[k];
                    float w = T * alpha;
                    accR += w * Cv.x;
                    accG += w * Cv.y;
                    accB += w * Cv.z;
                    acc  += w;
                    dnum += w * Cv.w;
                    T *= (1.0f - alpha);
                }
            }
        }

        if (cbase + NTHR < cnt) {
            if (__syncthreads_and(T < 1e-7f)) break;
        }
    }

    int pix = py * W_IMG + px;
    g_p4[seg][pix] = make_float4(accR, accG, accB, acc);
    g_p2[seg][pix] = make_float2(dnum, T);
}

// ---------------------------------------------------------------------------
// Kernel 5: combine segments + background + clamps.
// out = part0 + T0 * part1   (transmittance is multiplicative)
// ---------------------------------------------------------------------------
__global__ void __launch_bounds__(256)
combine_kernel(const float* __restrict__ bg, float* __restrict__ out)
{
    int pix = blockIdx.x * blockDim.x + threadIdx.x;
    if (pix >= NPIX) return;

    float4 a0 = g_p4[0][pix];
    float2 b0 = g_p2[0][pix];
    float4 a1 = g_p4[1][pix];
    float2 b1 = g_p2[1][pix];

    float t0 = b0.y;
    float accR = a0.x + t0 * a1.x;
    float accG = a0.y + t0 * a1.y;
    float accB = a0.z + t0 * a1.z;
    float acc  = a0.w + t0 * a1.w;
    float dnum = b0.x + t0 * b1.x;

    float bgr = bg[0], bgg = bg[1], bgb = bg[2];
    float Rv = accR + (1.0f - acc) * bgr;
    float Gv = accG + (1.0f - acc) * bgg;
    float Bv = accB + (1.0f - acc) * bgb;
    Rv = fminf(fmaxf(Rv, 0.0f), 1.0f);
    Gv = fminf(fmaxf(Gv, 0.0f), 1.0f);
    Bv = fminf(fmaxf(Bv, 0.0f), 1.0f);
    float A = fminf(fmaxf(acc, 0.0f), 1.0f);
    float depth = (acc > 0.0f) ? (dnum / fmaxf(acc, 1e-8f)) : 0.0f;

    int o = pix * 5;
    out[o+0] = Rv;
    out[o+1] = Gv;
    out[o+2] = Bv;
    out[o+3] = A;
    out[o+4] = depth;
}

// ---------------------------------------------------------------------------
extern "C" void kernel_launch(void* const* d_in, const int* in_sizes, int n_in,
                              void* d_out, int out_size)
{
    const float* xyz     = (const float*)d_in[0];
    const float* cov     = (const float*)d_in[1];
    const float* colors  = (const float*)d_in[2];
    const float* opacity = (const float*)d_in[3];
    const float* w2c     = (const float*)d_in[4];
    const float* focal   = (const float*)d_in[5];
    const float* pp      = (const float*)d_in[6];
    const float* bg      = (const float*)d_in[7];
    float* out = (float*)d_out;

    prep_kernel<<<NG / 64, 64>>>(xyz, cov, colors, opacity, w2c, focal, pp);
    rank_kernel<<<dim3(16, 16), 256>>>();
    scatter_kernel<<<NG / 256, 256>>>();
    render_kernel<<<NBLK * NSEG, NTHR>>>();
    combine_kernel<<<NPIX / 256, 256>>>(bg, out);
}

// round 14
// speedup vs baseline: 1.1266x; 1.1228x over previous
#include <cuda_runtime.h>
#include <math.h>

#define NG 4096
#define W_IMG 256
#define H_IMG 256
#define TSZ 64
#define NBLK 256           // 16x16 grid of 16x16-pixel blocks
#define NTHR 256
#define GPT 16             // gaussians per thread in strip scan

// unsorted per-gaussian data (attr-packed)
__device__ unsigned long long g_key[NG];  // (z-order uint << 12) | index
__device__ int    g_rank[NG];
__device__ float4 g_tA[NG];     // mx,my,c00,c11
__device__ float2 g_tQ[NG];     // csum,op
__device__ float4 g_tR[NG];     // r,g,b,z
__device__ unsigned g_tpbx[NG]; // packed bbox bytes {xmin,xmax,ymin,ymax}, tile-expanded if clipped

// z-sorted
__device__ float4 g_sA[NG];
__device__ float2 g_sQ[NG];
__device__ float4 g_sR[NG];
__device__ unsigned g_spbx[NG];

// ---------------------------------------------------------------------------
// Kernel 1: projection / preprocessing
// ---------------------------------------------------------------------------
__global__ void prep_kernel(const float* __restrict__ xyz,
                            const float* __restrict__ cov_world,
                            const float* __restrict__ colors,
                            const float* __restrict__ opacity,
                            const float* __restrict__ w2c,
                            const float* __restrict__ focal,
                            const float* __restrict__ pp)
{
    int i = blockIdx.x * blockDim.x + threadIdx.x;
    if (i >= NG) return;

    float R00 = w2c[0],  R01 = w2c[1],  R02 = w2c[2],  t0 = w2c[3];
    float R10 = w2c[4],  R11 = w2c[5],  R12 = w2c[6],  t1 = w2c[7];
    float R20 = w2c[8],  R21 = w2c[9],  R22 = w2c[10], t2 = w2c[11];

    float p0 = xyz[i*3+0], p1 = xyz[i*3+1], p2 = xyz[i*3+2];
    float cam0 = R00*p0 + R01*p1 + R02*p2 + t0;
    float cam1 = R10*p0 + R11*p1 + R12*p2 + t1;
    float cam2 = R20*p0 + R21*p1 + R22*p2 + t2;

    float zr = cam2;
    float z  = fmaxf(zr, 1e-6f);
    float fx = focal[0], fy = focal[1];
    float mx = fx * cam0 / z + pp[0];
    float my = fy * cam1 / z + pp[1];

    float S[3][3];
    #pragma unroll
    for (int r = 0; r < 3; r++)
        #pragma unroll
        for (int c = 0; c < 3; c++)
            S[r][c] = cov_world[i*9 + r*3 + c];

    float Rm[3][3] = {{R00,R01,R02},{R10,R11,R12},{R20,R21,R22}};
    float M[3][3], C[3][3];
    #pragma unroll
    for (int r = 0; r < 3; r++)
        #pragma unroll
        for (int c = 0; c < 3; c++)
            M[r][c] = Rm[r][0]*S[0][c] + Rm[r][1]*S[1][c] + Rm[r][2]*S[2][c];
    #pragma unroll
    for (int r = 0; r < 3; r++)
        #pragma unroll
        for (int c = 0; c < 3; c++)
            C[r][c] = M[r][0]*Rm[c][0] + M[r][1]*Rm[c][1] + M[r][2]*Rm[c][2];

    float J00 = fx / z, J02 = -fx * cam0 / (z * z);
    float J11 = fy / z, J12 = -fy * cam1 / (z * z);
    float t0v0 = J00*C[0][0] + J02*C[2][0];
    float t0v1 = J00*C[0][1] + J02*C[2][1];
    float t0v2 = J00*C[0][2] + J02*C[2][2];
    float t1v0 = J11*C[1][0] + J12*C[2][0];
    float t1v1 = J11*C[1][1] + J12*C[2][1];
    float t1v2 = J11*C[1][2] + J12*C[2][2];

    float a = t0v0*J00 + t0v2*J02 + 0.3f;
    float b = t0v1*J11 + t0v2*J12;
    float c = t1v0*J00 + t1v2*J02;
    float d = t1v1*J11 + t1v2*J12 + 0.3f;

    float disc   = sqrtf(fmaxf(0.25f*(a-d)*(a-d) + b*c, 0.0f));
    float maxeig = fmaxf(0.5f*(a+d) + disc, 1e-8f);
    float rraw   = 3.0f * sqrtf(maxeig);
    float radius = fminf(rraw, 64.0f);
    float det    = a*d - b*c;
    float c00  = d / det;
    float c11  = a / det;
    float csum = (-b - c) / det;

    float opv = opacity[i];
    bool valid = (zr > 0.1f) && (opv > 1e-4f) && (radius > 0.25f);
    valid = valid && (mx + radius >= -1.0f) && (mx - radius < (float)W_IMG + 1.0f);
    valid = valid && (my + radius >= -1.0f) && (my - radius < (float)H_IMG + 1.0f);

    float radii = ceilf(radius);
    int ixmin = (int)fminf(fmaxf(floorf(mx - radii), 0.0f), 255.0f);
    int ixmax = (int)fminf(fmaxf(ceilf (mx + radii), 0.0f), 255.0f);
    int iymin = (int)fminf(fmaxf(floorf(my - radii), 0.0f), 255.0f);
    int iymax = (int)fminf(fmaxf(ceilf (my + radii), 0.0f), 255.0f);

    // Clipped radius: 3-sigma ellipse may exceed bbox, so the per-block bbox
    // refine is unsound; expand bbox to tile boundaries, making the block
    // interval test exactly equivalent to the reference tile-overlap test.
    if (rraw > 64.0f) {
        ixmin &= ~63; iymin &= ~63;
        ixmax |=  63; iymax |=  63;
    }

    unsigned pbx;
    if (!valid) {
        pbx = 255u | (0u << 8) | (255u << 16) | (0u << 24);   // empty bbox
    } else {
        pbx = (unsigned)ixmin | ((unsigned)ixmax << 8) |
              ((unsigned)iymin << 16) | ((unsigned)iymax << 24);
    }

    // order-preserving uint mapping of float z (total order; stable via index)
    unsigned zb = __float_as_uint(zr);
    unsigned zk = (zb & 0x80000000u) ? ~zb : (zb | 0x80000000u);
    g_key[i]  = ((unsigned long long)zk << 12) | (unsigned)i;
    g_rank[i] = 0;
    g_tA[i] = make_float4(mx, my, c00, c11);
    g_tQ[i] = make_float2(csum, opv);
    g_tR[i] = make_float4(colors[i*3+0], colors[i*3+1], colors[i*3+2], zr);
    g_tpbx[i] = pbx;
}

// ---------------------------------------------------------------------------
// Kernel 2: partial stable rank via 64-bit key compares.
// grid = (16 i-chunks, 16 j-chunks); each block: 256 i vs one 256 j-chunk.
// ---------------------------------------------------------------------------
__global__ void __launch_bounds__(256)
rank_kernel()
{
    __shared__ unsigned long long ksh[256];
    const int ibase = blockIdx.x * 256;
    const int jbase = blockIdx.y * 256;
    const int tid = threadIdx.x;

    ksh[tid] = g_key[jbase + tid];
    __syncthreads();

    const unsigned long long ki = g_key[ibase + tid];
    const ulonglong2* k2 = (const ulonglong2*)ksh;
    int partial = 0;
    #pragma unroll 16
    for (int j2 = 0; j2 < 128; j2++) {
        ulonglong2 v = k2[j2];
        partial += (v.x < ki);
        partial += (v.y < ki);
    }
    atomicAdd(&g_rank[ibase + tid], partial);
}

// ---------------------------------------------------------------------------
// Kernel 3: scatter to sorted order
// ---------------------------------------------------------------------------
__global__ void scatter_kernel()
{
    int i = blockIdx.x * blockDim.x + threadIdx.x;
    if (i >= NG) return;
    int r = g_rank[i];
    g_sA[r]   = g_tA[i];
    g_sQ[r]   = g_tQ[i];
    g_sR[r]   = g_tR[i];
    g_spbx[r] = g_tpbx[i];
}

// ---------------------------------------------------------------------------
// Kernel 4: fused bin + rasterize. One block = one 16x16 pixel block.
// Phase A: strip-scan predicates (SIMD byte compares), block scan, ordered
//          index list in shared.
// Phase B: unroll-4 composite, per-gaussian warp-any skip (miss-skipping
//          preserved), colors/z loaded only on hit.
// ---------------------------------------------------------------------------
#define COMPOSITE_ONE(Pv, Qv, CvIdx)                                     \
    do {                                                                 \
        float dx = cx - (Pv).x;                                          \
        float dy = cy - (Pv).y;                                          \
        float maha = dx*dx*(Pv).z + dy*dy*(Pv).w + dx*dy*(Qv).x;         \
        bool hit = (maha <= 9.0f);   /* NaN -> false, matches where */   \
        if (__any_sync(0xffffffffu, hit)) {                              \
            float alpha = fminf(__expf(-0.5f * maha) * (Qv).y, 0.99f);   \
            if (hit && alpha >= (1.0f / 255.0f)) {                       \
                float4 Cv = sR[CvIdx];                                   \
                float w = T * alpha;                                     \
                accR += w * Cv.x;                                        \
                accG += w * Cv.y;                                        \
                accB += w * Cv.z;                                        \
                acc  += w;                                               \
                dnum += w * Cv.w;                                        \
                T *= (1.0f - alpha);                                     \
            }                                                            \
        }                                                                \
    } while (0)

__global__ void __launch_bounds__(NTHR)
render_kernel(const float* __restrict__ bg, float* __restrict__ out)
{
    const int bl  = blockIdx.x;
    const int bx0 = (bl & 15) * 16;
    const int by0 = (bl >> 4) * 16;

    const int tid  = threadIdx.x;
    const int warp = tid >> 5;
    const int lane = tid & 31;

    __shared__ short s_idx[NG];
    __shared__ int wsum[8], wpre[8];
    __shared__ float4 sP[NTHR];
    __shared__ float2 sQ[NTHR];
    __shared__ float4 sR[NTHR];

    // SIMD thresholds: bytes of pbx are {xmin, xmax, ymin, ymax}
    const unsigned Tge = ((unsigned)bx0 << 8) | ((unsigned)by0 << 24);
    const unsigned Tle = (unsigned)(bx0 + 15) | (255u << 8) |
                         ((unsigned)(by0 + 15) << 16) | (255u << 24);

    // --- Phase A: predicates, 4 x LDG.128 per thread = 16 gaussians ---
    const uint4* pb4 = (const uint4*)g_spbx;
    unsigned mmask = 0;
    int lc = 0;
    #pragma unroll
    for (int q = 0; q < 4; q++) {
        uint4 p = pb4[tid * 4 + q];
        unsigned w0 = __vcmpgeu4(p.x, Tge) & __vcmpleu4(p.x, Tle);
        unsigned w1 = __vcmpgeu4(p.y, Tge) & __vcmpleu4(p.y, Tle);
        unsigned w2 = __vcmpgeu4(p.z, Tge) & __vcmpleu4(p.z, Tle);
        unsigned w3 = __vcmpgeu4(p.w, Tge) & __vcmpleu4(p.w, Tle);
        if (w0 == 0xFFFFFFFFu) { mmask |= 1u << (q*4+0); lc++; }
        if (w1 == 0xFFFFFFFFu) { mmask |= 1u << (q*4+1); lc++; }
        if (w2 == 0xFFFFFFFFu) { mmask |= 1u << (q*4+2); lc++; }
        if (w3 == 0xFFFFFFFFu) { mmask |= 1u << (q*4+3); lc++; }
    }

    // --- block-wide exclusive scan of lc ---
    int v = lc;
    #pragma unroll
    for (int d2 = 1; d2 < 32; d2 <<= 1) {
        int n = __shfl_up_sync(0xffffffffu, v, d2);
        if (lane >= d2) v += n;
    }
    if (lane == 31) wsum[warp] = v;
    __syncthreads();
    if (tid < 8) {
        int s = wsum[tid];
        #pragma unroll
        for (int d2 = 1; d2 < 8; d2 <<= 1) {
            int n = __shfl_up_sync(0xffu, s, d2);
            if (tid >= d2) s += n;
        }
        wpre[tid] = s;
    }
    __syncthreads();

    int offset = ((warp == 0) ? 0 : wpre[warp - 1]) + (v - lc);
    const int base = tid * GPT;
    unsigned mm = mmask;
    while (mm) {
        int k = __ffs(mm) - 1;
        mm &= mm - 1;
        s_idx[offset++] = (short)(base + k);
    }
    const int cnt = wpre[7];
    __syncthreads();

    // --- Phase B: composite (unroll-4, per-gaussian votes) ---
    const int px = bx0 + (tid & 15);
    const int py = by0 + (tid >> 4);
    const float cx = (float)px + 0.5f;
    const float cy = (float)py + 0.5f;

    float T = 1.0f;
    float accR = 0.f, accG = 0.f, accB = 0.f, acc = 0.f, dnum = 0.f;

    for (int cbase = 0; cbase < cnt; cbase += NTHR) {
        int li = cbase + tid;
        if (li < cnt) {
            int gi = s_idx[li];
            sP[tid] = g_sA[gi];
            sQ[tid] = g_sQ[gi];
            sR[tid] = g_sR[gi];
        }
        __syncthreads();

        int m = cnt - cbase; if (m > NTHR) m = NTHR;
        int k = 0;
        for (; k + 4 <= m; k += 4) {
            float4 P0 = sP[k],   P1 = sP[k+1], P2 = sP[k+2], P3 = sP[k+3];
            float2 Q0 = sQ[k],   Q1 = sQ[k+1], Q2 = sQ[k+2], Q3 = sQ[k+3];
            COMPOSITE_ONE(P0, Q0, k);
            COMPOSITE_ONE(P1, Q1, k+1);
            COMPOSITE_ONE(P2, Q2, k+2);
            COMPOSITE_ONE(P3, Q3, k+3);
        }
        for (; k < m; k++) {
            float4 P0 = sP[k];
            float2 Q0 = sQ[k];
            COMPOSITE_ONE(P0, Q0, k);
        }

        if (cbase + NTHR < cnt) {
            if (__syncthreads_and(T < 1e-7f)) break;
        }
    }

    float bgr = bg[0], bgg = bg[1], bgb = bg[2];
    float Rv = accR + (1.0f - acc) * bgr;
    float Gv = accG + (1.0f - acc) * bgg;
    float Bv = accB + (1.0f - acc) * bgb;
    Rv = fminf(fmaxf(Rv, 0.0f), 1.0f);
    Gv = fminf(fmaxf(Gv, 0.0f), 1.0f);
    Bv = fminf(fmaxf(Bv, 0.0f), 1.0f);
    float A = fminf(fmaxf(acc, 0.0f), 1.0f);
    float depth = (acc > 0.0f) ? (dnum / fmaxf(acc, 1e-8f)) : 0.0f;

    int o = (py * W_IMG + px) * 5;
    out[o+0] = Rv;
    out[o+1] = Gv;
    out[o+2] = Bv;
    out[o+3] = A;
    out[o+4] = depth;
}

// ---------------------------------------------------------------------------
extern "C" void kernel_launch(void* const* d_in, const int* in_sizes, int n_in,
                              void* d_out, int out_size)
{
    const float* xyz     = (const float*)d_in[0];
    const float* cov     = (const float*)d_in[1];
    const float* colors  = (const float*)d_in[2];
    const float* opacity = (const float*)d_in[3];
    const float* w2c     = (const float*)d_in[4];
    const float* focal   = (const float*)d_in[5];
    const float* pp      = (const float*)d_in[6];
    const float* bg      = (const float*)d_in[7];
    float* out = (float*)d_out;

    prep_kernel<<<NG / 64, 64>>>(xyz, cov, colors, opacity, w2c, focal, pp);
    rank_kernel<<<dim3(16, 16), 256>>>();
    scatter_kernel<<<NG / 256, 256>>>();
    render_kernel<<<NBLK, NTHR>>>(bg, out);
}

// round 15
// speedup vs baseline: 1.1540x; 1.0244x over previous
#include <cuda_runtime.h>
#include <math.h>

#define NG 4096
#define W_IMG 256
#define H_IMG 256
#define TSZ 64
#define NBLK 256           // 16x16 grid of 16x16-pixel blocks
#define NTHR 256
#define GPT 16             // gaussians per thread in strip scan

// unsorted per-gaussian data (attr-packed)
__device__ unsigned long long g_key[NG];  // (z-order uint << 12) | index
__device__ int    g_rank[NG];
__device__ float4 g_tA[NG];     // mx,my,c00,c11
__device__ float2 g_tQ[NG];     // csum,op
__device__ float4 g_tR[NG];     // r,g,b,z
__device__ unsigned g_tpbx[NG]; // packed bbox bytes {xmin,xmax,ymin,ymax}, tile-expanded if clipped

// z-sorted
__device__ float4 g_sA[NG];
__device__ float2 g_sQ[NG];
__device__ float4 g_sR[NG];
__device__ unsigned g_spbx[NG];

// ---------------------------------------------------------------------------
// Kernel 1: projection / preprocessing
// ---------------------------------------------------------------------------
__global__ void prep_kernel(const float* __restrict__ xyz,
                            const float* __restrict__ cov_world,
                            const float* __restrict__ colors,
                            const float* __restrict__ opacity,
                            const float* __restrict__ w2c,
                            const float* __restrict__ focal,
                            const float* __restrict__ pp)
{
    int i = blockIdx.x * blockDim.x + threadIdx.x;
    if (i >= NG) return;

    float R00 = w2c[0],  R01 = w2c[1],  R02 = w2c[2],  t0 = w2c[3];
    float R10 = w2c[4],  R11 = w2c[5],  R12 = w2c[6],  t1 = w2c[7];
    float R20 = w2c[8],  R21 = w2c[9],  R22 = w2c[10], t2 = w2c[11];

    float p0 = xyz[i*3+0], p1 = xyz[i*3+1], p2 = xyz[i*3+2];
    float cam0 = R00*p0 + R01*p1 + R02*p2 + t0;
    float cam1 = R10*p0 + R11*p1 + R12*p2 + t1;
    float cam2 = R20*p0 + R21*p1 + R22*p2 + t2;

    float zr = cam2;
    float z  = fmaxf(zr, 1e-6f);
    float fx = focal[0], fy = focal[1];
    float mx = fx * cam0 / z + pp[0];
    float my = fy * cam1 / z + pp[1];

    float S[3][3];
    #pragma unroll
    for (int r = 0; r < 3; r++)
        #pragma unroll
        for (int c = 0; c < 3; c++)
            S[r][c] = cov_world[i*9 + r*3 + c];

    float Rm[3][3] = {{R00,R01,R02},{R10,R11,R12},{R20,R21,R22}};
    float M[3][3], C[3][3];
    #pragma unroll
    for (int r = 0; r < 3; r++)
        #pragma unroll
        for (int c = 0; c < 3; c++)
            M[r][c] = Rm[r][0]*S[0][c] + Rm[r][1]*S[1][c] + Rm[r][2]*S[2][c];
    #pragma unroll
    for (int r = 0; r < 3; r++)
        #pragma unroll
        for (int c = 0; c < 3; c++)
            C[r][c] = M[r][0]*Rm[c][0] + M[r][1]*Rm[c][1] + M[r][2]*Rm[c][2];

    float J00 = fx / z, J02 = -fx * cam0 / (z * z);
    float J11 = fy / z, J12 = -fy * cam1 / (z * z);
    float t0v0 = J00*C[0][0] + J02*C[2][0];
    float t0v1 = J00*C[0][1] + J02*C[2][1];
    float t0v2 = J00*C[0][2] + J02*C[2][2];
    float t1v0 = J11*C[1][0] + J12*C[2][0];
    float t1v1 = J11*C[1][1] + J12*C[2][1];
    float t1v2 = J11*C[1][2] + J12*C[2][2];

    float a = t0v0*J00 + t0v2*J02 + 0.3f;
    float b = t0v1*J11 + t0v2*J12;
    float c = t1v0*J00 + t1v2*J02;
    float d = t1v1*J11 + t1v2*J12 + 0.3f;

    float disc   = sqrtf(fmaxf(0.25f*(a-d)*(a-d) + b*c, 0.0f));
    float maxeig = fmaxf(0.5f*(a+d) + disc, 1e-8f);
    float rraw   = 3.0f * sqrtf(maxeig);
    float radius = fminf(rraw, 64.0f);
    float det    = a*d - b*c;
    float c00  = d / det;
    float c11  = a / det;
    float csum = (-b - c) / det;

    float opv = opacity[i];
    bool valid = (zr > 0.1f) && (opv > 1e-4f) && (radius > 0.25f);
    valid = valid && (mx + radius >= -1.0f) && (mx - radius < (float)W_IMG + 1.0f);
    valid = valid && (my + radius >= -1.0f) && (my - radius < (float)H_IMG + 1.0f);

    float radii = ceilf(radius);
    int ixmin = (int)fminf(fmaxf(floorf(mx - radii), 0.0f), 255.0f);
    int ixmax = (int)fminf(fmaxf(ceilf (mx + radii), 0.0f), 255.0f);
    int iymin = (int)fminf(fmaxf(floorf(my - radii), 0.0f), 255.0f);
    int iymax = (int)fminf(fmaxf(ceilf (my + radii), 0.0f), 255.0f);

    // Clipped radius: 3-sigma ellipse may exceed bbox, so the per-block bbox
    // refine is unsound; expand bbox to tile boundaries, making the block
    // interval test exactly equivalent to the reference tile-overlap test.
    if (rraw > 64.0f) {
        ixmin &= ~63; iymin &= ~63;
        ixmax |=  63; iymax |=  63;
    }

    unsigned pbx;
    if (!valid) {
        pbx = 255u | (0u << 8) | (255u << 16) | (0u << 24);   // empty bbox
    } else {
        pbx = (unsigned)ixmin | ((unsigned)ixmax << 8) |
              ((unsigned)iymin << 16) | ((unsigned)iymax << 24);
    }

    // order-preserving uint mapping of float z (total order; stable via index)
    unsigned zb = __float_as_uint(zr);
    unsigned zk = (zb & 0x80000000u) ? ~zb : (zb | 0x80000000u);
    g_key[i]  = ((unsigned long long)zk << 12) | (unsigned)i;
    g_rank[i] = 0;
    g_tA[i] = make_float4(mx, my, c00, c11);
    g_tQ[i] = make_float2(csum, opv);
    g_tR[i] = make_float4(colors[i*3+0], colors[i*3+1], colors[i*3+2], zr);
    g_tpbx[i] = pbx;
}

// ---------------------------------------------------------------------------
// Kernel 2: partial stable rank via 64-bit key compares.
// grid = (16 i-chunks, 16 j-chunks); each block: 256 i vs one 256 j-chunk.
// ---------------------------------------------------------------------------
__global__ void __launch_bounds__(256)
rank_kernel()
{
    __shared__ unsigned long long ksh[256];
    const int ibase = blockIdx.x * 256;
    const int jbase = blockIdx.y * 256;
    const int tid = threadIdx.x;

    ksh[tid] = g_key[jbase + tid];
    __syncthreads();

    const unsigned long long ki = g_key[ibase + tid];
    const ulonglong2* k2 = (const ulonglong2*)ksh;
    int partial = 0;
    #pragma unroll 16
    for (int j2 = 0; j2 < 128; j2++) {
        ulonglong2 v = k2[j2];
        partial += (v.x < ki);
        partial += (v.y < ki);
    }
    atomicAdd(&g_rank[ibase + tid], partial);
}

// ---------------------------------------------------------------------------
// Kernel 3: scatter to sorted order
// ---------------------------------------------------------------------------
__global__ void scatter_kernel()
{
    int i = blockIdx.x * blockDim.x + threadIdx.x;
    if (i >= NG) return;
    int r = g_rank[i];
    g_sA[r]   = g_tA[i];
    g_sQ[r]   = g_tQ[i];
    g_sR[r]   = g_tR[i];
    g_spbx[r] = g_tpbx[i];
}

// ---------------------------------------------------------------------------
// Kernel 4: fused bin + rasterize. One block = one 16x16 pixel block.
// Phase A: strip-scan predicates (SIMD byte compares), block scan, ordered
//          index list in shared.
// Phase B: simple composite loop; each WARP owns a compact 8x4 pixel quad
//          so the per-gaussian __any vote skips far more whole-warp misses.
// ---------------------------------------------------------------------------
__global__ void __launch_bounds__(NTHR)
render_kernel(const float* __restrict__ bg, float* __restrict__ out)
{
    const int bl  = blockIdx.x;
    const int bx0 = (bl & 15) * 16;
    const int by0 = (bl >> 4) * 16;

    const int tid  = threadIdx.x;
    const int warp = tid >> 5;
    const int lane = tid & 31;

    __shared__ short s_idx[NG];
    __shared__ int wsum[8], wpre[8];
    __shared__ float4 sP[NTHR];
    __shared__ float2 sQ[NTHR];
    __shared__ float4 sR[NTHR];

    // SIMD thresholds: bytes of pbx are {xmin, xmax, ymin, ymax}
    const unsigned Tge = ((unsigned)bx0 << 8) | ((unsigned)by0 << 24);
    const unsigned Tle = (unsigned)(bx0 + 15) | (255u << 8) |
                         ((unsigned)(by0 + 15) << 16) | (255u << 24);

    // --- Phase A: predicates, 4 x LDG.128 per thread = 16 gaussians ---
    const uint4* pb4 = (const uint4*)g_spbx;
    unsigned mmask = 0;
    int lc = 0;
    #pragma unroll
    for (int q = 0; q < 4; q++) {
        uint4 p = pb4[tid * 4 + q];
        unsigned w0 = __vcmpgeu4(p.x, Tge) & __vcmpleu4(p.x, Tle);
        unsigned w1 = __vcmpgeu4(p.y, Tge) & __vcmpleu4(p.y, Tle);
        unsigned w2 = __vcmpgeu4(p.z, Tge) & __vcmpleu4(p.z, Tle);
        unsigned w3 = __vcmpgeu4(p.w, Tge) & __vcmpleu4(p.w, Tle);
        if (w0 == 0xFFFFFFFFu) { mmask |= 1u << (q*4+0); lc++; }
        if (w1 == 0xFFFFFFFFu) { mmask |= 1u << (q*4+1); lc++; }
        if (w2 == 0xFFFFFFFFu) { mmask |= 1u << (q*4+2); lc++; }
        if (w3 == 0xFFFFFFFFu) { mmask |= 1u << (q*4+3); lc++; }
    }

    // --- block-wide exclusive scan of lc ---
    int v = lc;
    #pragma unroll
    for (int d2 = 1; d2 < 32; d2 <<= 1) {
        int n = __shfl_up_sync(0xffffffffu, v, d2);
        if (lane >= d2) v += n;
    }
    if (lane == 31) wsum[warp] = v;
    __syncthreads();
    if (tid < 8) {
        int s = wsum[tid];
        #pragma unroll
        for (int d2 = 1; d2 < 8; d2 <<= 1) {
            int n = __shfl_up_sync(0xffu, s, d2);
            if (tid >= d2) s += n;
        }
        wpre[tid] = s;
    }
    __syncthreads();

    int offset = ((warp == 0) ? 0 : wpre[warp - 1]) + (v - lc);
    const int base = tid * GPT;
    unsigned mm = mmask;
    while (mm) {
        int k = __ffs(mm) - 1;
        mm &= mm - 1;
        s_idx[offset++] = (short)(base + k);
    }
    const int cnt = wpre[7];
    __syncthreads();

    // --- Phase B: composite ---
    // Warp-compact pixel mapping: each warp owns an 8x4 quad.
    //   px = bx0 + tid[2:0] + tid[5]*8 ; py = by0 + tid[4:3] + tid[7:6]*4
    const int px = bx0 + (tid & 7) + ((tid >> 5) & 1) * 8;
    const int py = by0 + ((tid >> 3) & 3) + (tid >> 6) * 4;
    const float cx = (float)px + 0.5f;
    const float cy = (float)py + 0.5f;

    float T = 1.0f;
    float accR = 0.f, accG = 0.f, accB = 0.f, acc = 0.f, dnum = 0.f;

    for (int cbase = 0; cbase < cnt; cbase += NTHR) {
        int li = cbase + tid;
        if (li < cnt) {
            int gi = s_idx[li];
            sP[tid] = g_sA[gi];
            sQ[tid] = g_sQ[gi];
            sR[tid] = g_sR[gi];
        }
        __syncthreads();

        int m = cnt - cbase; if (m > NTHR) m = NTHR;
        for (int k = 0; k < m; k++) {
            float4 P = sP[k];
            float dx = cx - P.x;
            float dy = cy - P.y;
            float2 Q = sQ[k];
            float maha = dx*dx*P.z + dy*dy*P.w + dx*dy*Q.x;
            bool hit = (maha <= 9.0f);        // NaN -> false, matches jnp.where
            if (__any_sync(0xffffffffu, hit)) {
                float alpha = fminf(__expf(-0.5f * maha) * Q.y, 0.99f);
                if (hit && alpha >= (1.0f / 255.0f)) {
                    float4 Cv = sR[k];
                    float w = T * alpha;
                    accR += w * Cv.x;
                    accG += w * Cv.y;
                    accB += w * Cv.z;
                    acc  += w;
                    dnum += w * Cv.w;
                    T *= (1.0f - alpha);
                }
            }
        }

        if (cbase + NTHR < cnt) {
            if (__syncthreads_and(T < 1e-7f)) break;
        }
    }

    float bgr = bg[0], bgg = bg[1], bgb = bg[2];
    float Rv = accR + (1.0f - acc) * bgr;
    float Gv = accG + (1.0f - acc) * bgg;
    float Bv = accB + (1.0f - acc) * bgb;
    Rv = fminf(fmaxf(Rv, 0.0f), 1.0f);
    Gv = fminf(fmaxf(Gv, 0.0f), 1.0f);
    Bv = fminf(fmaxf(Bv, 0.0f), 1.0f);
    float A = fminf(fmaxf(acc, 0.0f), 1.0f);
    float depth = (acc > 0.0f) ? (dnum / fmaxf(acc, 1e-8f)) : 0.0f;

    int o = (py * W_IMG + px) * 5;
    out[o+0] = Rv;
    out[o+1] = Gv;
    out[o+2] = Bv;
    out[o+3] = A;
    out[o+4] = depth;
}

// ---------------------------------------------------------------------------
extern "C" void kernel_launch(void* const* d_in, const int* in_sizes, int n_in,
                              void* d_out, int out_size)
{
    const float* xyz     = (const float*)d_in[0];
    const float* cov     = (const float*)d_in[1];
    const float* colors  = (const float*)d_in[2];
    const float* opacity = (const float*)d_in[3];
    const float* w2c     = (const float*)d_in[4];
    const float* focal   = (const float*)d_in[5];
    const float* pp      = (const float*)d_in[6];
    const float* bg      = (const float*)d_in[7];
    float* out = (float*)d_out;

    prep_kernel<<<128, 32>>>(xyz, cov, colors, opacity, w2c, focal, pp);
    rank_kernel<<<dim3(16, 16), 256>>>();
    scatter_kernel<<<NG / 256, 256>>>();
    render_kernel<<<NBLK, NTHR>>>(bg, out);
}

// round 16
// speedup vs baseline: 1.1691x; 1.0130x over previous
#include <cuda_runtime.h>
#include <math.h>

#define NG 4096
#define W_IMG 256
#define H_IMG 256
#define TSZ 64
#define NBLK 256           // 16x16 grid of 16x16-pixel blocks
#define NTHR 256
#define GPT 16             // gaussians per thread in strip scan

// unsorted per-gaussian data (attr-packed)
__device__ unsigned long long g_key[NG];  // (z-order uint << 12) | index
__device__ int    g_rank[NG];
__device__ float4 g_tA[NG];     // mx,my,c00,c11
__device__ float2 g_tQ[NG];     // csum,op
__device__ float4 g_tR[NG];     // r,g,b,z
__device__ unsigned g_tpbx[NG]; // packed bbox bytes {xmin,xmax,ymin,ymax}

// z-sorted
__device__ float4 g_sA[NG];
__device__ float2 g_sQ[NG];
__device__ float4 g_sR[NG];
__device__ unsigned g_spbx[NG];

// ---------------------------------------------------------------------------
// Kernel 1: projection / preprocessing
// ---------------------------------------------------------------------------
__global__ void prep_kernel(const float* __restrict__ xyz,
                            const float* __restrict__ cov_world,
                            const float* __restrict__ colors,
                            const float* __restrict__ opacity,
                            const float* __restrict__ w2c,
                            const float* __restrict__ focal,
                            const float* __restrict__ pp)
{
    int i = blockIdx.x * blockDim.x + threadIdx.x;
    if (i >= NG) return;

    float R00 = w2c[0],  R01 = w2c[1],  R02 = w2c[2],  t0 = w2c[3];
    float R10 = w2c[4],  R11 = w2c[5],  R12 = w2c[6],  t1 = w2c[7];
    float R20 = w2c[8],  R21 = w2c[9],  R22 = w2c[10], t2 = w2c[11];

    float p0 = xyz[i*3+0], p1 = xyz[i*3+1], p2 = xyz[i*3+2];
    float cam0 = R00*p0 + R01*p1 + R02*p2 + t0;
    float cam1 = R10*p0 + R11*p1 + R12*p2 + t1;
    float cam2 = R20*p0 + R21*p1 + R22*p2 + t2;

    float zr = cam2;
    float z  = fmaxf(zr, 1e-6f);
    float fx = focal[0], fy = focal[1];
    float mx = fx * cam0 / z + pp[0];
    float my = fy * cam1 / z + pp[1];

    float S[3][3];
    #pragma unroll
    for (int r = 0; r < 3; r++)
        #pragma unroll
        for (int c = 0; c < 3; c++)
            S[r][c] = cov_world[i*9 + r*3 + c];

    float Rm[3][3] = {{R00,R01,R02},{R10,R11,R12},{R20,R21,R22}};
    float M[3][3], C[3][3];
    #pragma unroll
    for (int r = 0; r < 3; r++)
        #pragma unroll
        for (int c = 0; c < 3; c++)
            M[r][c] = Rm[r][0]*S[0][c] + Rm[r][1]*S[1][c] + Rm[r][2]*S[2][c];
    #pragma unroll
    for (int r = 0; r < 3; r++)
        #pragma unroll
        for (int c = 0; c < 3; c++)
            C[r][c] = M[r][0]*Rm[c][0] + M[r][1]*Rm[c][1] + M[r][2]*Rm[c][2];

    float J00 = fx / z, J02 = -fx * cam0 / (z * z);
    float J11 = fy / z, J12 = -fy * cam1 / (z * z);
    float t0v0 = J00*C[0][0] + J02*C[2][0];
    float t0v1 = J00*C[0][1] + J02*C[2][1];
    float t0v2 = J00*C[0][2] + J02*C[2][2];
    float t1v0 = J11*C[1][0] + J12*C[2][0];
    float t1v1 = J11*C[1][1] + J12*C[2][1];
    float t1v2 = J11*C[1][2] + J12*C[2][2];

    float a = t0v0*J00 + t0v2*J02 + 0.3f;
    float b = t0v1*J11 + t0v2*J12;
    float c = t1v0*J00 + t1v2*J02;
    float d = t1v1*J11 + t1v2*J12 + 0.3f;

    float disc   = sqrtf(fmaxf(0.25f*(a-d)*(a-d) + b*c, 0.0f));
    float maxeig = fmaxf(0.5f*(a+d) + disc, 1e-8f);
    float rraw   = 3.0f * sqrtf(maxeig);
    float radius = fminf(rraw, 64.0f);
    float det    = a*d - b*c;
    float c00  = d / det;
    float c11  = a / det;
    float csum = (-b - c) / det;

    float opv = opacity[i];
    bool valid = (zr > 0.1f) && (opv > 1e-4f) && (radius > 0.25f);
    valid = valid && (mx + radius >= -1.0f) && (mx - radius < (float)W_IMG + 1.0f);
    valid = valid && (my + radius >= -1.0f) && (my - radius < (float)H_IMG + 1.0f);

    // --- base bbox, exact reference semantics ---
    float radii = ceilf(radius);
    int ixmin = (int)fminf(fmaxf(floorf(mx - radii), 0.0f), 255.0f);
    int ixmax = (int)fminf(fmaxf(ceilf (mx + radii), 0.0f), 255.0f);
    int iymin = (int)fminf(fmaxf(floorf(my - radii), 0.0f), 255.0f);
    int iymax = (int)fminf(fmaxf(ceilf (my + radii), 0.0f), 255.0f);

    // Clipped radius: the block bbox test must degrade to the reference
    // tile-overlap test -> expand base bbox to tile boundaries.
    if (rraw > 64.0f) {
        ixmin &= ~63; iymin &= ~63;
        ixmax |=  63; iymax |=  63;
    }

    unsigned pbx;
    if (!valid) {
        pbx = 255u | (0u << 8) | (255u << 16) | (0u << 24);   // empty bbox
    } else {
        // --- opacity-aware per-axis ellipse support, intersected with base ---
        // contribution requires maha <= t, t = min(9, 2 ln(255 op)); exact
        // x-extent of {d: d^T Q d <= t} is sqrt(t*a), y-extent sqrt(t*d).
        // Any contributing pixel lies in BOTH the ellipse box and the base
        // (tile-expanded) box, so their intersection is a valid predicate box.
        bool qok = (det > 0.0f) && (a > 0.0f) && (d > 0.0f);
        if (qok) {
            float tthr = fminf(9.0f, 2.0f * logf(255.0f * opv) + 0.02f);
            if (tthr <= 0.0f) {
                // alpha < 1/255 everywhere (gw <= 1 since Q pos-def): cull
                ixmin = 255; ixmax = 0; iymin = 255; iymax = 0;
            } else {
                float extx = sqrtf(tthr * a) * 1.0005f + 1.0f;
                float exty = sqrtf(tthr * d) * 1.0005f + 1.0f;
                int exmin = (int)fminf(fmaxf(floorf(mx - extx), 0.0f), 255.0f);
                int exmax = (int)fminf(fmaxf(ceilf (mx + extx), 0.0f), 255.0f);
                int eymin = (int)fminf(fmaxf(floorf(my - exty), 0.0f), 255.0f);
                int eymax = (int)fminf(fmaxf(ceilf (my + exty), 0.0f), 255.0f);
                ixmin = max(ixmin, exmin); ixmax = min(ixmax, exmax);
                iymin = max(iymin, eymin); iymax = min(iymax, eymax);
            }
        }
        pbx = (unsigned)ixmin | ((unsigned)ixmax << 8) |
              ((unsigned)iymin << 16) | ((unsigned)iymax << 24);
    }

    // order-preserving uint mapping of float z (total order; stable via index)
    unsigned zb = __float_as_uint(zr);
    unsigned zk = (zb & 0x80000000u) ? ~zb : (zb | 0x80000000u);
    g_key[i]  = ((unsigned long long)zk << 12) | (unsigned)i;
    g_rank[i] = 0;
    g_tA[i] = make_float4(mx, my, c00, c11);
    g_tQ[i] = make_float2(csum, opv);
    g_tR[i] = make_float4(colors[i*3+0], colors[i*3+1], colors[i*3+2], zr);
    g_tpbx[i] = pbx;
}

// ---------------------------------------------------------------------------
// Kernel 2: partial stable rank via 64-bit key compares.
// grid = (16 i-chunks, 16 j-chunks); each block: 256 i vs one 256 j-chunk.
// ---------------------------------------------------------------------------
__global__ void __launch_bounds__(256)
rank_kernel()
{
    __shared__ unsigned long long ksh[256];
    const int ibase = blockIdx.x * 256;
    const int jbase = blockIdx.y * 256;
    const int tid = threadIdx.x;

    ksh[tid] = g_key[jbase + tid];
    __syncthreads();

    const unsigned long long ki = g_key[ibase + tid];
    const ulonglong2* k2 = (const ulonglong2*)ksh;
    int partial = 0;
    #pragma unroll 16
    for (int j2 = 0; j2 < 128; j2++) {
        ulonglong2 v = k2[j2];
        partial += (v.x < ki);
        partial += (v.y < ki);
    }
    atomicAdd(&g_rank[ibase + tid], partial);
}

// ---------------------------------------------------------------------------
// Kernel 3: scatter to sorted order
// ---------------------------------------------------------------------------
__global__ void scatter_kernel()
{
    int i = blockIdx.x * blockDim.x + threadIdx.x;
    if (i >= NG) return;
    int r = g_rank[i];
    g_sA[r]   = g_tA[i];
    g_sQ[r]   = g_tQ[i];
    g_sR[r]   = g_tR[i];
    g_spbx[r] = g_tpbx[i];
}

// ---------------------------------------------------------------------------
// Kernel 4: fused bin + rasterize. One block = one 16x16 pixel block.
// Phase A: strip-scan predicates (SIMD byte compares), block scan, ordered
//          index list in shared.
// Phase B: simple composite loop; each WARP owns a compact 8x4 pixel quad
//          so the per-gaussian __any vote skips more whole-warp misses.
// ---------------------------------------------------------------------------
__global__ void __launch_bounds__(NTHR)
render_kernel(const float* __restrict__ bg, float* __restrict__ out)
{
    const int bl  = blockIdx.x;
    const int bx0 = (bl & 15) * 16;
    const int by0 = (bl >> 4) * 16;

    const int tid  = threadIdx.x;
    const int warp = tid >> 5;
    const int lane = tid & 31;

    __shared__ short s_idx[NG];
    __shared__ int wsum[8], wpre[8];
    __shared__ float4 sP[NTHR];
    __shared__ float2 sQ[NTHR];
    __shared__ float4 sR[NTHR];

    // SIMD thresholds: bytes of pbx are {xmin, xmax, ymin, ymax}
    const unsigned Tge = ((unsigned)bx0 << 8) | ((unsigned)by0 << 24);
    const unsigned Tle = (unsigned)(bx0 + 15) | (255u << 8) |
                         ((unsigned)(by0 + 15) << 16) | (255u << 24);

    // --- Phase A: predicates, 4 x LDG.128 per thread = 16 gaussians ---
    const uint4* pb4 = (const uint4*)g_spbx;
    unsigned mmask = 0;
    int lc = 0;
    #pragma unroll
    for (int q = 0; q < 4; q++) {
        uint4 p = pb4[tid * 4 + q];
        unsigned w0 = __vcmpgeu4(p.x, Tge) & __vcmpleu4(p.x, Tle);
        unsigned w1 = __vcmpgeu4(p.y, Tge) & __vcmpleu4(p.y, Tle);
        unsigned w2 = __vcmpgeu4(p.z, Tge) & __vcmpleu4(p.z, Tle);
        unsigned w3 = __vcmpgeu4(p.w, Tge) & __vcmpleu4(p.w, Tle);
        if (w0 == 0xFFFFFFFFu) { mmask |= 1u << (q*4+0); lc++; }
        if (w1 == 0xFFFFFFFFu) { mmask |= 1u << (q*4+1); lc++; }
        if (w2 == 0xFFFFFFFFu) { mmask |= 1u << (q*4+2); lc++; }
        if (w3 == 0xFFFFFFFFu) { mmask |= 1u << (q*4+3); lc++; }
    }

    // --- block-wide exclusive scan of lc ---
    int v = lc;
    #pragma unroll
    for (int d2 = 1; d2 < 32; d2 <<= 1) {
        int n = __shfl_up_sync(0xffffffffu, v, d2);
        if (lane >= d2) v += n;
    }
    if (lane == 31) wsum[warp] = v;
    __syncthreads();
    if (tid < 8) {
        int s = wsum[tid];
        #pragma unroll
        for (int d2 = 1; d2 < 8; d2 <<= 1) {
            int n = __shfl_up_sync(0xffu, s, d2);
            if (tid >= d2) s += n;
        }
        wpre[tid] = s;
    }
    __syncthreads();

    int offset = ((warp == 0) ? 0 : wpre[warp - 1]) + (v - lc);
    const int base = tid * GPT;
    unsigned mm = mmask;
    while (mm) {
        int k = __ffs(mm) - 1;
        mm &= mm - 1;
        s_idx[offset++] = (short)(base + k);
    }
    const int cnt = wpre[7];
    __syncthreads();

    // --- Phase B: composite ---
    // Warp-compact pixel mapping: each warp owns an 8x4 quad.
    const int px = bx0 + (tid & 7) + ((tid >> 5) & 1) * 8;
    const int py = by0 + ((tid >> 3) & 3) + (tid >> 6) * 4;
    const float cx = (float)px + 0.5f;
    const float cy = (float)py + 0.5f;

    float T = 1.0f;
    float accR = 0.f, accG = 0.f, accB = 0.f, acc = 0.f, dnum = 0.f;

    for (int cbase = 0; cbase < cnt; cbase += NTHR) {
        int li = cbase + tid;
        if (li < cnt) {
            int gi = s_idx[li];
            sP[tid] = g_sA[gi];
            sQ[tid] = g_sQ[gi];
            sR[tid] = g_sR[gi];
        }
        __syncthreads();

        int m = cnt - cbase; if (m > NTHR) m = NTHR;
        for (int k = 0; k < m; k++) {
            float4 P = sP[k];
            float dx = cx - P.x;
            float dy = cy - P.y;
            float2 Q = sQ[k];
            float maha = dx*dx*P.z + dy*dy*P.w + dx*dy*Q.x;
            bool hit = (maha <= 9.0f);        // NaN -> false, matches jnp.where
            if (__any_sync(0xffffffffu, hit)) {
                float alpha = fminf(__expf(-0.5f * maha) * Q.y, 0.99f);
                if (hit && alpha >= (1.0f / 255.0f)) {
                    float4 Cv = sR[k];
                    float w = T * alpha;
                    accR += w * Cv.x;
                    accG += w * Cv.y;
                    accB += w * Cv.z;
                    acc  += w;
                    dnum += w * Cv.w;
                    T *= (1.0f - alpha);
                }
            }
        }

        if (cbase + NTHR < cnt) {
            if (__syncthreads_and(T < 1e-7f)) break;
        }
    }

    float bgr = bg[0], bgg = bg[1], bgb = bg[2];
    float Rv = accR + (1.0f - acc) * bgr;
    float Gv = accG + (1.0f - acc) * bgg;
    float Bv = accB + (1.0f - acc) * bgb;
    Rv = fminf(fmaxf(Rv, 0.0f), 1.0f);
    Gv = fminf(fmaxf(Gv, 0.0f), 1.0f);
    Bv = fminf(fmaxf(Bv, 0.0f), 1.0f);
    float A = fminf(fmaxf(acc, 0.0f), 1.0f);
    float depth = (acc > 0.0f) ? (dnum / fmaxf(acc, 1e-8f)) : 0.0f;

    int o = (py * W_IMG + px) * 5;
    out[o+0] = Rv;
    out[o+1] = Gv;
    out[o+2] = Bv;
    out[o+3] = A;
    out[o+4] = depth;
}

// ---------------------------------------------------------------------------
extern "C" void kernel_launch(void* const* d_in, const int* in_sizes, int n_in,
                              void* d_out, int out_size)
{
    const float* xyz     = (const float*)d_in[0];
    const float* cov     = (const float*)d_in[1];
    const float* colors  = (const float*)d_in[2];
    const float* opacity = (const float*)d_in[3];
    const float* w2c     = (const float*)d_in[4];
    const float* focal   = (const float*)d_in[5];
    const float* pp      = (const float*)d_in[6];
    const float* bg      = (const float*)d_in[7];
    float* out = (float*)d_out;

    prep_kernel<<<128, 32>>>(xyz, cov, colors, opacity, w2c, focal, pp);
    rank_kernel<<<dim3(16, 16), 256>>>();
    scatter_kernel<<<NG / 256, 256>>>();
    render_kernel<<<NBLK, NTHR>>>(bg, out);
}